// round 12
// baseline (speedup 1.0000x reference)
#include <cuda_runtime.h>
#include <cuda_fp16.h>
#include <math.h>
#include <stdint.h>

#define NROWS 4096
#define NDIM  2048
#define TEMP_INV 2.0f
#define QSCALE 64.0f           // fp8 quantization scale
#define QS2_INV (1.0f / (QSCALE * QSCALE))

// ---------------- device scratch ----------------
__device__ __align__(1024) uint8_t g_A8[NROWS * NDIM];   // e4m3, normalized * 64
__device__ __align__(1024) uint8_t g_C8[NROWS * NDIM];   // e4m3, normalized * 64
__device__ float  g_invB[NROWS];
__device__ float  g_csA[NDIM];
__device__ float  g_csB[NDIM];
__device__ double g_S;
__device__ float  g_pos;

// ---------------- raw-PTX fp8 conversion ----------------
__device__ __forceinline__ uint16_t pack_e4m3x2(float hi, float lo) {
    uint16_t r;
    asm("cvt.rn.satfinite.e4m3x2.f32 %0, %1, %2;" : "=h"(r) : "f"(hi), "f"(lo));
    return r;
}
__device__ __forceinline__ float2 unpack_e4m3x2(uint16_t v) {
    uint32_t h2;
    asm("cvt.rn.f16x2.e4m3x2 %0, %1;" : "=r"(h2) : "h"(v));
    __half2 h = *reinterpret_cast<__half2*>(&h2);
    return __half22float2(h);
}

// ---------------- zero accumulators ----------------
__global__ void zero_kernel() {
    int i = blockIdx.x * blockDim.x + threadIdx.x;
    if (i < NDIM) { g_csA[i] = 0.f; g_csB[i] = 0.f; }
    if (i == 0)   { g_S = 0.0; g_pos = 0.f; }
}

// ---------------- fused norm + normalize -> e4m3 (*64) ----------------
__global__ __launch_bounds__(256) void fuse_norm_kernel(const float* __restrict__ X,
                                                        uint8_t* __restrict__ out) {
    int row = blockIdx.x;
    int tid = threadIdx.x;
    const float4* p = reinterpret_cast<const float4*>(X + (size_t)row * NDIM);
    float4 a = p[tid * 2 + 0];
    float4 b = p[tid * 2 + 1];
    float s = a.x * a.x + a.y * a.y + a.z * a.z + a.w * a.w
            + b.x * b.x + b.y * b.y + b.z * b.z + b.w * b.w;
    for (int off = 16; off; off >>= 1) s += __shfl_xor_sync(0xffffffffu, s, off);
    __shared__ float red[8];
    __shared__ float s_inv;
    if ((tid & 31) == 0) red[tid >> 5] = s;
    __syncthreads();
    if (tid == 0) {
        float t = 0.f;
        #pragma unroll
        for (int w = 0; w < 8; w++) t += red[w];
        s_inv = rsqrtf(t) * QSCALE;
    }
    __syncthreads();
    float inv = s_inv;

    uint16_t q0 = pack_e4m3x2(a.y * inv, a.x * inv);
    uint16_t q1 = pack_e4m3x2(a.w * inv, a.z * inv);
    uint16_t q2 = pack_e4m3x2(b.y * inv, b.x * inv);
    uint16_t q3 = pack_e4m3x2(b.w * inv, b.z * inv);
    uint2 o;
    o.x = (uint32_t)q0 | ((uint32_t)q1 << 16);
    o.y = (uint32_t)q2 | ((uint32_t)q3 << 16);
    reinterpret_cast<uint2*>(out + (size_t)row * NDIM)[tid] = o;
}

// ---------------- per-row inverse L2 norm (B only) ----------------
__global__ void row_norms_kernel(const float* __restrict__ X, float* __restrict__ inv) {
    int row = blockIdx.x;
    const float4* p = reinterpret_cast<const float4*>(X + (size_t)row * NDIM);
    float s = 0.f;
    for (int i = threadIdx.x; i < NDIM / 4; i += blockDim.x) {
        float4 v = p[i];
        s += v.x * v.x + v.y * v.y + v.z * v.z + v.w * v.w;
    }
    for (int off = 16; off; off >>= 1) s += __shfl_xor_sync(0xffffffffu, s, off);
    __shared__ float red[8];
    if ((threadIdx.x & 31) == 0) red[threadIdx.x >> 5] = s;
    __syncthreads();
    if (threadIdx.x == 0) {
        float t = 0.f;
        #pragma unroll
        for (int w = 0; w < 8; w++) t += red[w];
        inv[row] = rsqrtf(t);
    }
}

// ---------------- column sums ----------------
// 4 columns per thread via uint32 loads (full-sector efficiency)
__global__ void colsum_fp8_kernel(const uint8_t* __restrict__ X8,
                                  float* __restrict__ cs) {
    int d4 = blockIdx.x * blockDim.x + threadIdx.x;   // quad index, < NDIM/4
    int i0 = blockIdx.y * 32;
    float s0 = 0.f, s1 = 0.f, s2 = 0.f, s3 = 0.f;
    #pragma unroll 4
    for (int i = 0; i < 32; i++) {
        uint32_t v = *reinterpret_cast<const uint32_t*>(&X8[(size_t)(i0 + i) * NDIM + d4 * 4]);
        float2 lo = unpack_e4m3x2((uint16_t)(v & 0xffff));
        float2 hi = unpack_e4m3x2((uint16_t)(v >> 16));
        s0 += lo.x; s1 += lo.y; s2 += hi.x; s3 += hi.y;
    }
    atomicAdd(&cs[d4 * 4 + 0], s0 * (1.0f / QSCALE));
    atomicAdd(&cs[d4 * 4 + 1], s1 * (1.0f / QSCALE));
    atomicAdd(&cs[d4 * 4 + 2], s2 * (1.0f / QSCALE));
    atomicAdd(&cs[d4 * 4 + 3], s3 * (1.0f / QSCALE));
}

__global__ void colsum_f32_kernel(const float* __restrict__ X,
                                  const float* __restrict__ inv,
                                  float* __restrict__ cs) {
    int d  = blockIdx.x * blockDim.x + threadIdx.x;
    int i0 = blockIdx.y * (NROWS / 32);
    float s = 0.f;
    #pragma unroll 4
    for (int i = 0; i < NROWS / 32; i++)
        s += X[(size_t)(i0 + i) * NDIM + d] * inv[i0 + i];
    atomicAdd(&cs[d], s);
}

__global__ void posdot_kernel() {
    float s = 0.f;
    for (int d = threadIdx.x; d < NDIM; d += 256) s += g_csA[d] * g_csB[d];
    for (int off = 16; off; off >>= 1) s += __shfl_xor_sync(0xffffffffu, s, off);
    __shared__ float red[8];
    if ((threadIdx.x & 31) == 0) red[threadIdx.x >> 5] = s;
    __syncthreads();
    if (threadIdx.x == 0) {
        float t = 0.f;
        #pragma unroll
        for (int w = 0; w < 8; w++) t += red[w];
        g_pos = t;
    }
}

// ---------------- pipelined FP8 mma.sync GEMM + exp-sum ----------------
// CTA tile 128x128, BK=64 fp8, 4-stage cp.async pipeline, 256 threads,
// 2 CTAs/SM. K-loop unrolled by STAGES so stage offsets constant-fold;
// all smem/global addresses precomputed once per thread.
#define BM 128
#define BN 128
#define BK 64
#define STAGES 4
#define AST 80                         // bytes per smem row (64 data + 16 pad)
#define A_BYTES_S (BM * AST)           // 10240
#define B_BYTES_S (BN * AST)           // 10240
#define STAGE_BYTES (A_BYTES_S + B_BYTES_S)  // 20480
#define SMEM_BYTES (STAGES * STAGE_BYTES)    // 81920
#define KTILES (NDIM / BK)             // 32

__device__ __forceinline__ uint32_t cvta_s(const void* p) {
    uint32_t a;
    asm("{ .reg .u64 t; cvta.to.shared.u64 t, %1; cvt.u32.u64 %0, t; }" : "=r"(a) : "l"(p));
    return a;
}
__device__ __forceinline__ void cp16(uint32_t dst, const void* src) {
    asm volatile("cp.async.cg.shared.global [%0], [%1], 16;" :: "r"(dst), "l"(src));
}
__device__ __forceinline__ void ldmatrix_x4(uint32_t r[4], uint32_t addr) {
    asm volatile("ldmatrix.sync.aligned.m8n8.x4.shared.b16 {%0,%1,%2,%3}, [%4];"
                 : "=r"(r[0]), "=r"(r[1]), "=r"(r[2]), "=r"(r[3]) : "r"(addr));
}

__global__ __launch_bounds__(256, 2) void gemm_expsum_kernel() {
    extern __shared__ uint8_t sm[];
    const int tid  = threadIdx.x;
    const int wid  = tid >> 5;
    const int lane = tid & 31;
    const int wm   = (wid & 1) * 64;     // 2 warps in M
    const int wn   = (wid >> 1) * 32;    // 4 warps in N
    const int bm   = blockIdx.y * BM;
    const int bn   = blockIdx.x * BN;

    float acc[16][4];
    #pragma unroll
    for (int i = 0; i < 16; i++)
        #pragma unroll
        for (int j = 0; j < 4; j++) acc[i][j] = 0.f;

    const uint32_t smb = cvta_s(sm);

    // ---- precomputed per-thread addresses ----
    const int lr = tid >> 2;            // 0..63
    const int lc = (tid & 3) * 16;      // 16B chunk within 64B row
    const uint32_t dA0 = smb + lr * AST + lc;
    const uint32_t dA1 = dA0 + 64 * AST;
    const uint32_t dB0 = dA0 + A_BYTES_S;
    const uint32_t dB1 = dB0 + 64 * AST;
    const uint8_t* pA0 = g_A8 + (size_t)(bm + lr) * NDIM + lc;
    const uint8_t* pA1 = pA0 + (size_t)64 * NDIM;
    const uint8_t* pB0 = g_C8 + (size_t)(bn + lr) * NDIM + lc;
    const uint8_t* pB1 = pB0 + (size_t)64 * NDIM;

    // ldmatrix base offsets (stage 0, kb 0)
    uint32_t aoff[4];
    #pragma unroll
    for (int mt = 0; mt < 4; mt++)
        aoff[mt] = smb + (wm + mt * 16 + (lane & 15)) * AST + (lane >> 4) * 16;
    uint32_t boff[2];
    #pragma unroll
    for (int ntp = 0; ntp < 2; ntp++)
        boff[ntp] = smb + A_BYTES_S +
                    (wn + ntp * 16 + (lane >> 4) * 8 + (lane & 7)) * AST +
                    ((lane >> 3) & 1) * 16;

    #define LOAD_STAGE(kt, s) do {                                   \
        const int off = (kt) * BK;                                   \
        cp16(dA0 + (s) * STAGE_BYTES, pA0 + off);                    \
        cp16(dA1 + (s) * STAGE_BYTES, pA1 + off);                    \
        cp16(dB0 + (s) * STAGE_BYTES, pB0 + off);                    \
        cp16(dB1 + (s) * STAGE_BYTES, pB1 + off);                    \
        asm volatile("cp.async.commit_group;" ::: "memory");         \
    } while (0)

    LOAD_STAGE(0, 0);
    LOAD_STAGE(1, 1);
    LOAD_STAGE(2, 2);
    asm volatile("cp.async.wait_group %0;" :: "n"(STAGES - 2) : "memory");
    __syncthreads();

    for (int kt4 = 0; kt4 < KTILES; kt4 += STAGES) {
        #pragma unroll
        for (int ss = 0; ss < STAGES; ss++) {
            const int kt = kt4 + ss;
            const int nx = kt + STAGES - 1;
            if (nx < KTILES) LOAD_STAGE(nx, (ss + STAGES - 1) & (STAGES - 1));

            const uint32_t sbase = ss * STAGE_BYTES;   // compile-time

            #pragma unroll
            for (int ks = 0; ks < 2; ks++) {
                const int kb = ks * 32;                // compile-time
                uint32_t bfrag[4][2];
                #pragma unroll
                for (int ntp = 0; ntp < 2; ntp++) {
                    uint32_t r4[4];
                    ldmatrix_x4(r4, boff[ntp] + sbase + kb);
                    bfrag[ntp * 2 + 0][0] = r4[0];
                    bfrag[ntp * 2 + 0][1] = r4[1];
                    bfrag[ntp * 2 + 1][0] = r4[2];
                    bfrag[ntp * 2 + 1][1] = r4[3];
                }
                #pragma unroll
                for (int mt = 0; mt < 4; mt++) {
                    uint32_t af[4];
                    ldmatrix_x4(af, aoff[mt] + sbase + kb);
                    #pragma unroll
                    for (int nt = 0; nt < 4; nt++) {
                        float* c = acc[mt * 4 + nt];
                        asm volatile(
                            "mma.sync.aligned.m16n8k32.row.col.f32.e4m3.e4m3.f32 "
                            "{%0,%1,%2,%3}, {%4,%5,%6,%7}, {%8,%9}, {%0,%1,%2,%3};"
                            : "+f"(c[0]), "+f"(c[1]), "+f"(c[2]), "+f"(c[3])
                            : "r"(af[0]), "r"(af[1]), "r"(af[2]), "r"(af[3]),
                              "r"(bfrag[nt][0]), "r"(bfrag[nt][1]));
                    }
                }
            }
            asm volatile("cp.async.wait_group %0;" :: "n"(STAGES - 2) : "memory");
            __syncthreads();
        }
    }

    // epilogue: sum exp(2*sim); acc = sim * QSCALE^2 -> scale back
    float local = 0.f;
    #pragma unroll
    for (int i = 0; i < 16; i++)
        #pragma unroll
        for (int j = 0; j < 4; j++)
            local += __expf(acc[i][j] * (TEMP_INV * QS2_INV));

    for (int off = 16; off; off >>= 1) local += __shfl_xor_sync(0xffffffffu, local, off);
    __shared__ float red[8];
    if (lane == 0) red[wid] = local;
    __syncthreads();
    if (tid == 0) {
        float t = 0.f;
        #pragma unroll
        for (int w = 0; w < 8; w++) t += red[w];
        atomicAdd(&g_S, (double)t);
    }
}

// ---------------- final scalar ----------------
__global__ void final_kernel(float* __restrict__ out) {
    double n2 = (double)NROWS * (double)NROWS;
    double loss = log(g_S) - (double)g_pos * (double)TEMP_INV / n2;
    out[0] = (float)loss;
}

// ---------------- host ----------------
extern "C" void kernel_launch(void* const* d_in, const int* in_sizes, int n_in,
                              void* d_out, int out_size) {
    const float* xA = (const float*)d_in[0];  // x_source
    const float* xB = (const float*)d_in[1];  // x_bc_target
    const float* xC = (const float*)d_in[2];  // x_raw_target
    float* out = (float*)d_out;

    // GEMM kept as 4th launch so ncu (-s 5) lands on it.
    fuse_norm_kernel<<<NROWS, 256>>>(xA, g_A8);
    fuse_norm_kernel<<<NROWS, 256>>>(xC, g_C8);
    zero_kernel<<<8, 256>>>();

    cudaFuncSetAttribute(gemm_expsum_kernel,
                         cudaFuncAttributeMaxDynamicSharedMemorySize, SMEM_BYTES);
    {
        dim3 grid(NROWS / BN, NROWS / BM);
        gemm_expsum_kernel<<<grid, 256, SMEM_BYTES>>>();
    }

    row_norms_kernel<<<NROWS, 256>>>(xB, g_invB);
    {
        dim3 gridp(NDIM / 4 / 256, NROWS / 32);
        colsum_fp8_kernel<<<gridp, 256>>>(g_A8, g_csA);
        dim3 grid(NDIM / 256, 32);
        colsum_f32_kernel<<<grid, 256>>>(xB, g_invB, g_csB);
    }
    posdot_kernel<<<1, 256>>>();

    final_kernel<<<1, 1>>>(out);
}

// round 14
// speedup vs baseline: 1.1403x; 1.1403x over previous
#include <cuda_runtime.h>
#include <cuda_fp16.h>
#include <math.h>
#include <stdint.h>

#define NROWS 4096
#define NDIM  2048
#define TEMP_INV 2.0f
#define QSCALE 64.0f           // fp8 quantization scale
#define QS2_INV (1.0f / (QSCALE * QSCALE))

// ---------------- device scratch ----------------
__device__ __align__(1024) uint8_t g_A8[NROWS * NDIM];   // e4m3, normalized * 64
__device__ __align__(1024) uint8_t g_C8[NROWS * NDIM];   // e4m3, normalized * 64
__device__ __align__(1024) uint8_t g_B8[NROWS * NDIM];   // e4m3, normalized * 64
__device__ float  g_csA[NDIM];
__device__ float  g_csB[NDIM];
__device__ double g_S;

// ---------------- raw-PTX fp8 conversion ----------------
__device__ __forceinline__ uint16_t pack_e4m3x2(float hi, float lo) {
    uint16_t r;
    asm("cvt.rn.satfinite.e4m3x2.f32 %0, %1, %2;" : "=h"(r) : "f"(hi), "f"(lo));
    return r;
}
__device__ __forceinline__ float2 unpack_e4m3x2(uint16_t v) {
    uint32_t h2;
    asm("cvt.rn.f16x2.e4m3x2 %0, %1;" : "=r"(h2) : "h"(v));
    __half2 h = *reinterpret_cast<__half2*>(&h2);
    return __half22float2(h);
}

// ---------------- zero accumulators ----------------
__global__ void zero_kernel() {
    int i = blockIdx.x * blockDim.x + threadIdx.x;
    if (i < NDIM) { g_csA[i] = 0.f; g_csB[i] = 0.f; }
    if (i == 0)   { g_S = 0.0; }
}

// ---------------- fused norm + normalize -> e4m3 (*64) ----------------
__global__ __launch_bounds__(256) void fuse_norm_kernel(const float* __restrict__ X,
                                                        uint8_t* __restrict__ out) {
    int row = blockIdx.x;
    int tid = threadIdx.x;
    const float4* p = reinterpret_cast<const float4*>(X + (size_t)row * NDIM);
    float4 a = p[tid * 2 + 0];
    float4 b = p[tid * 2 + 1];
    float s = a.x * a.x + a.y * a.y + a.z * a.z + a.w * a.w
            + b.x * b.x + b.y * b.y + b.z * b.z + b.w * b.w;
    for (int off = 16; off; off >>= 1) s += __shfl_xor_sync(0xffffffffu, s, off);
    __shared__ float red[8];
    __shared__ float s_inv;
    if ((tid & 31) == 0) red[tid >> 5] = s;
    __syncthreads();
    if (tid == 0) {
        float t = 0.f;
        #pragma unroll
        for (int w = 0; w < 8; w++) t += red[w];
        s_inv = rsqrtf(t) * QSCALE;
    }
    __syncthreads();
    float inv = s_inv;

    uint16_t q0 = pack_e4m3x2(a.y * inv, a.x * inv);
    uint16_t q1 = pack_e4m3x2(a.w * inv, a.z * inv);
    uint16_t q2 = pack_e4m3x2(b.y * inv, b.x * inv);
    uint16_t q3 = pack_e4m3x2(b.w * inv, b.z * inv);
    uint2 o;
    o.x = (uint32_t)q0 | ((uint32_t)q1 << 16);
    o.y = (uint32_t)q2 | ((uint32_t)q3 << 16);
    reinterpret_cast<uint2*>(out + (size_t)row * NDIM)[tid] = o;
}

// ---------------- column sums (fp8 source; exact R10-measured version) ----
__global__ void colsum_fp8_kernel(const uint8_t* __restrict__ X8,
                                  float* __restrict__ cs) {
    int d2 = blockIdx.x * blockDim.x + threadIdx.x;   // pair index
    int i0 = blockIdx.y * (NROWS / 32);
    float s0 = 0.f, s1 = 0.f;
    #pragma unroll 4
    for (int i = 0; i < NROWS / 32; i++) {
        uint16_t v = *reinterpret_cast<const uint16_t*>(&X8[(size_t)(i0 + i) * NDIM + d2 * 2]);
        float2 f = unpack_e4m3x2(v);
        s0 += f.x; s1 += f.y;
    }
    atomicAdd(&cs[d2 * 2 + 0], s0 * (1.0f / QSCALE));
    atomicAdd(&cs[d2 * 2 + 1], s1 * (1.0f / QSCALE));
}

// ---------------- pipelined FP8 mma.sync GEMM + exp-sum ----------------
// CTA tile 128x128, k-tile = 128 fp8, 3-stage cp.async pipeline, ONE
// barrier per k-tile (16 total), 256 threads, 2 CTAs/SM.
#define BM 128
#define BN 128
#define BKB 128                        // k-bytes per tile
#define AST2 144                       // bytes per smem row (128 data + 16 pad)
#define A_B2 (BM * AST2)               // 18432
#define STG2 (2 * A_B2)                // 36864 (A + B)
#define NSTAGE 3
#define SMEM2 (NSTAGE * STG2)          // 110592
#define KT2 (NDIM / BKB)               // 16

__device__ __forceinline__ uint32_t cvta_s(const void* p) {
    uint32_t a;
    asm("{ .reg .u64 t; cvta.to.shared.u64 t, %1; cvt.u32.u64 %0, t; }" : "=r"(a) : "l"(p));
    return a;
}
__device__ __forceinline__ void cp16(uint32_t dst, const void* src) {
    asm volatile("cp.async.cg.shared.global [%0], [%1], 16;" :: "r"(dst), "l"(src));
}
__device__ __forceinline__ void ldmatrix_x4(uint32_t r[4], uint32_t addr) {
    asm volatile("ldmatrix.sync.aligned.m8n8.x4.shared.b16 {%0,%1,%2,%3}, [%4];"
                 : "=r"(r[0]), "=r"(r[1]), "=r"(r[2]), "=r"(r[3]) : "r"(addr));
}

__global__ __launch_bounds__(256, 2) void gemm_expsum_kernel() {
    extern __shared__ uint8_t sm[];
    const int tid  = threadIdx.x;
    const int wid  = tid >> 5;
    const int lane = tid & 31;
    const int wm   = (wid & 1) * 64;     // 2 warps in M
    const int wn   = (wid >> 1) * 32;    // 4 warps in N
    const int bm   = blockIdx.y * BM;
    const int bn   = blockIdx.x * BN;

    float acc[16][4];
    #pragma unroll
    for (int i = 0; i < 16; i++)
        #pragma unroll
        for (int j = 0; j < 4; j++) acc[i][j] = 0.f;

    const uint32_t smb = cvta_s(sm);

    // ---- cp.async slots: row = (tid>>3) + r*32, chunk = (tid&7)*16 ----
    const int lrr = tid >> 3;            // 0..31
    const int lcc = (tid & 7) * 16;      // 16B chunk within 128B row
    const uint32_t dA = smb + lrr * AST2 + lcc;
    const uint32_t dB = dA + A_B2;
    const uint8_t* pA = g_A8 + (size_t)(bm + lrr) * NDIM + lcc;
    const uint8_t* pB = g_C8 + (size_t)(bn + lrr) * NDIM + lcc;

    // ldmatrix base offsets (stage 0, ks 0)
    uint32_t aoff[4];
    #pragma unroll
    for (int mt = 0; mt < 4; mt++)
        aoff[mt] = smb + (wm + mt * 16 + (lane & 15)) * AST2 + (lane >> 4) * 16;
    uint32_t boff[2];
    #pragma unroll
    for (int ntp = 0; ntp < 2; ntp++)
        boff[ntp] = smb + A_B2 +
                    (wn + ntp * 16 + (lane >> 4) * 8 + (lane & 7)) * AST2 +
                    ((lane >> 3) & 1) * 16;

    #define LOAD2(kt, s) do {                                        \
        const int off = (kt) * BKB;                                  \
        const uint32_t sb = (s) * STG2;                              \
        cp16(dA + sb,                 pA + off);                     \
        cp16(dA + sb + 32 * AST2,     pA + off + (size_t)32 * NDIM); \
        cp16(dA + sb + 64 * AST2,     pA + off + (size_t)64 * NDIM); \
        cp16(dA + sb + 96 * AST2,     pA + off + (size_t)96 * NDIM); \
        cp16(dB + sb,                 pB + off);                     \
        cp16(dB + sb + 32 * AST2,     pB + off + (size_t)32 * NDIM); \
        cp16(dB + sb + 64 * AST2,     pB + off + (size_t)64 * NDIM); \
        cp16(dB + sb + 96 * AST2,     pB + off + (size_t)96 * NDIM); \
        asm volatile("cp.async.commit_group;" ::: "memory");         \
    } while (0)

    LOAD2(0, 0);
    LOAD2(1, 1);

    #pragma unroll
    for (int kt = 0; kt < KT2; kt++) {
        // tile kt ready (only the newest group may still be pending)
        asm volatile("cp.async.wait_group 1;" ::: "memory");
        __syncthreads();   // publishes tile kt; frees stage of tile kt-1

        if (kt + 2 < KT2) LOAD2(kt + 2, (kt + 2) % NSTAGE);

        const uint32_t sbase = (kt % NSTAGE) * STG2;   // compile-time

        #pragma unroll
        for (int ks = 0; ks < 4; ks++) {
            const int kb = ks * 32;                    // compile-time
            uint32_t bfrag[4][2];
            #pragma unroll
            for (int ntp = 0; ntp < 2; ntp++) {
                uint32_t r4[4];
                ldmatrix_x4(r4, boff[ntp] + sbase + kb);
                bfrag[ntp * 2 + 0][0] = r4[0];
                bfrag[ntp * 2 + 0][1] = r4[1];
                bfrag[ntp * 2 + 1][0] = r4[2];
                bfrag[ntp * 2 + 1][1] = r4[3];
            }
            #pragma unroll
            for (int mt = 0; mt < 4; mt++) {
                uint32_t af[4];
                ldmatrix_x4(af, aoff[mt] + sbase + kb);
                #pragma unroll
                for (int nt = 0; nt < 4; nt++) {
                    float* c = acc[mt * 4 + nt];
                    asm volatile(
                        "mma.sync.aligned.m16n8k32.row.col.f32.e4m3.e4m3.f32 "
                        "{%0,%1,%2,%3}, {%4,%5,%6,%7}, {%8,%9}, {%0,%1,%2,%3};"
                        : "+f"(c[0]), "+f"(c[1]), "+f"(c[2]), "+f"(c[3])
                        : "r"(af[0]), "r"(af[1]), "r"(af[2]), "r"(af[3]),
                          "r"(bfrag[nt][0]), "r"(bfrag[nt][1]));
                }
            }
        }
    }

    // epilogue: sum exp(2*sim); acc = sim * QSCALE^2 -> scale back
    float local = 0.f;
    #pragma unroll
    for (int i = 0; i < 16; i++)
        #pragma unroll
        for (int j = 0; j < 4; j++)
            local += __expf(acc[i][j] * (TEMP_INV * QS2_INV));

    for (int off = 16; off; off >>= 1) local += __shfl_xor_sync(0xffffffffu, local, off);
    __shared__ float red[8];
    if (lane == 0) red[wid] = local;
    __syncthreads();
    if (tid == 0) {
        float t = 0.f;
        #pragma unroll
        for (int w = 0; w < 8; w++) t += red[w];
        atomicAdd(&g_S, (double)t);
    }
}

// ---------------- final scalar (posdot + loss) ----------------
__global__ __launch_bounds__(256) void final_kernel(float* __restrict__ out) {
    int tid = threadIdx.x;
    float s = 0.f;
    for (int d = tid; d < NDIM; d += 256) s += g_csA[d] * g_csB[d];
    for (int off = 16; off; off >>= 1) s += __shfl_xor_sync(0xffffffffu, s, off);
    __shared__ float red[8];
    if ((tid & 31) == 0) red[tid >> 5] = s;
    __syncthreads();
    if (tid == 0) {
        float pos = 0.f;
        #pragma unroll
        for (int w = 0; w < 8; w++) pos += red[w];
        double n2 = (double)NROWS * (double)NROWS;
        double loss = log(g_S) - (double)pos * (double)TEMP_INV / n2;
        out[0] = (float)loss;
    }
}

// ---------------- host ----------------
extern "C" void kernel_launch(void* const* d_in, const int* in_sizes, int n_in,
                              void* d_out, int out_size) {
    const float* xA = (const float*)d_in[0];  // x_source
    const float* xB = (const float*)d_in[1];  // x_bc_target
    const float* xC = (const float*)d_in[2];  // x_raw_target
    float* out = (float*)d_out;

    // GEMM kept as 4th launch so ncu (-s 5) lands on it.
    fuse_norm_kernel<<<NROWS, 256>>>(xA, g_A8);
    fuse_norm_kernel<<<NROWS, 256>>>(xC, g_C8);
    zero_kernel<<<8, 256>>>();

    cudaFuncSetAttribute(gemm_expsum_kernel,
                         cudaFuncAttributeMaxDynamicSharedMemorySize, SMEM2);
    {
        dim3 grid(NROWS / BN, NROWS / BM);
        gemm_expsum_kernel<<<grid, 256, SMEM2>>>();
    }

    fuse_norm_kernel<<<NROWS, 256>>>(xB, g_B8);
    {
        dim3 gridp(NDIM / 2 / 256, 32);
        colsum_fp8_kernel<<<gridp, 256>>>(g_A8, g_csA);
        colsum_fp8_kernel<<<gridp, 256>>>(g_B8, g_csB);
    }

    final_kernel<<<1, 256>>>(out);
}